// round 8
// baseline (speedup 1.0000x reference)
#include <cuda_runtime.h>
#include <cuda_bf16.h>
#include <cstdint>
#include <math.h>

#define HW 65536
#define IMG 256
#define CIN 256
#define CMID 64
#define NB 4

// Scratch (device globals; allocation is forbidden)
__device__ float g_y[NB * CMID * HW];      // conv1x1-in output (64 MiB)
__device__ float g_edge[NB * CMID * HW];   // unnormalized edge  (64 MiB)
__device__ unsigned g_maxbits;             // global max (float bits, values >= 0)
__device__ float g_csum[NB * CMID];        // per-(b,c) sums of edge
__device__ float g_seff[NB * CMID];        // sigmoid(se)*inv_max per (b,c)

// Pre-split weights (bf16 hi/lo)
__device__ __align__(16) __nv_bfloat16 g_win_hi[64 * 256];
__device__ __align__(16) __nv_bfloat16 g_win_lo[64 * 256];
__device__ __align__(16) __nv_bfloat16 g_wout_hi[64 * 64];
__device__ __align__(16) __nv_bfloat16 g_wout_lo[64 * 64];

// 1D gaussian (sigma=2, size=5), normalized: exp(-r^2/8)/sum
#define G0 0.15246915f
#define G1 0.22184120f
#define G2 0.25137913f

__global__ void k_init() {
    int t = threadIdx.x;
    if (t == 0) g_maxbits = 0u;
    if (t < NB * CMID) g_csum[t] = 0.0f;
}

// Split fp32 weights into bf16 hi/lo pairs.
__global__ void k_prep(const float* __restrict__ w_in, const float* __restrict__ w_out) {
    int i = blockIdx.x * 256 + threadIdx.x;
    if (i < 64 * 256) {
        float w = w_in[i];
        __nv_bfloat16 h = __float2bfloat16_rn(w);
        g_win_hi[i] = h;
        g_win_lo[i] = __float2bfloat16_rn(w - __bfloat162float(h));
    }
    if (i < 64 * 64) {
        float w = w_out[i];
        __nv_bfloat16 h = __float2bfloat16_rn(w);
        g_wout_hi[i] = h;
        g_wout_lo[i] = __float2bfloat16_rn(w - __bfloat162float(h));
    }
}

// ---------------------------------------------------------------------------
// Tensor-core 1x1 conv:  Y[b,o,p] = bias[o] + sum_c W[o,c] * X[b,c,p]
// M=64 (o), N_TILE=128 pixels, K=CK. 3-GEMM bf16 split for fp32-grade accuracy.
// 8 warps, each warp: m32 x n32. K processed in chunks of 64 with LDG prefetch.
// ---------------------------------------------------------------------------
__device__ __forceinline__ void mma_bf16(float* d, const uint32_t* a, const uint32_t* b) {
    asm volatile(
        "mma.sync.aligned.m16n8k16.row.col.f32.bf16.bf16.f32 "
        "{%0,%1,%2,%3}, {%4,%5,%6,%7}, {%8,%9}, {%0,%1,%2,%3};\n"
        : "+f"(d[0]), "+f"(d[1]), "+f"(d[2]), "+f"(d[3])
        : "r"(a[0]), "r"(a[1]), "r"(a[2]), "r"(a[3]), "r"(b[0]), "r"(b[1]));
}
__device__ __forceinline__ void ldsm_x4(uint32_t* r, uint32_t addr) {
    asm volatile("ldmatrix.sync.aligned.m8n8.x4.shared.b16 {%0,%1,%2,%3}, [%4];"
                 : "=r"(r[0]), "=r"(r[1]), "=r"(r[2]), "=r"(r[3]) : "r"(addr));
}
__device__ __forceinline__ void ldsm_x2t(uint32_t* r, uint32_t addr) {
    asm volatile("ldmatrix.sync.aligned.m8n8.x2.trans.shared.b16 {%0,%1}, [%2];"
                 : "=r"(r[0]), "=r"(r[1]) : "r"(addr));
}

template <int CK, bool SCALE>
__global__ __launch_bounds__(256, 2)
void k_gemm(const float* __restrict__ Xin, const float* __restrict__ bias,
            float* __restrict__ Yout) {
    constexpr int WP = CK + 8;     // W smem pitch (bf16 elems)
    constexpr int XP = 136;        // X smem pitch (bf16 elems), 16B-aligned rows
    constexpr int NCH = CK / 64;   // K chunks
    constexpr int NT = 128;        // pixels per block

    extern __shared__ char smem_raw[];
    __nv_bfloat16* sWh = (__nv_bfloat16*)smem_raw;
    __nv_bfloat16* sWl = sWh + 64 * WP;
    __nv_bfloat16* sXh = sWl + 64 * WP;
    __nv_bfloat16* sXl = sXh + 64 * XP;
    float* ssc = (float*)(sXl + 64 * XP);

    const int tid = threadIdx.x;
    const int lane = tid & 31;
    const int wid = tid >> 5;
    const int b = blockIdx.y;
    const int p0 = blockIdx.x * NT;

    const float* Xp = SCALE ? (const float*)g_edge : Xin;
    const __nv_bfloat16* gWh = SCALE ? g_wout_hi : g_win_hi;
    const __nv_bfloat16* gWl = SCALE ? g_wout_lo : g_win_lo;

    // Stage weights (bf16 hi/lo) into padded smem
    for (int i = tid; i < 64 * CK / 8; i += 256) {
        int m = i / (CK / 8);
        int c = (i % (CK / 8)) * 8;
        *(uint4*)&sWh[m * WP + c] = ((const uint4*)gWh)[i];
        *(uint4*)&sWl[m * WP + c] = ((const uint4*)gWl)[i];
    }
    if (SCALE && tid < CK) ssc[tid] = g_seff[b * CK + tid];

    // X chunk staging: thread -> (k row, 32 n-values contiguous)
    const int kr = tid >> 2;
    const int nn = (tid & 3) * 32;
    float vv[32];
    {
        const float* xp = Xp + ((size_t)b * CK + kr) * HW + p0 + nn;
#pragma unroll
        for (int q = 0; q < 8; q++) {
            float4 f = *(const float4*)(xp + q * 4);
            vv[4 * q + 0] = f.x; vv[4 * q + 1] = f.y;
            vv[4 * q + 2] = f.z; vv[4 * q + 3] = f.w;
        }
    }
    __syncthreads();   // weights + ssc ready

    const uint32_t uWh = (uint32_t)__cvta_generic_to_shared(sWh);
    const uint32_t uWl = (uint32_t)__cvta_generic_to_shared(sWl);
    const uint32_t uXh = (uint32_t)__cvta_generic_to_shared(sXh);
    const uint32_t uXl = (uint32_t)__cvta_generic_to_shared(sXl);

    const int m0 = (wid & 1) * 32;
    const int nc0 = (wid >> 1) * 32;
    float d[2][4][4];
#pragma unroll
    for (int mt = 0; mt < 2; mt++)
#pragma unroll
        for (int nt = 0; nt < 4; nt++)
#pragma unroll
            for (int r = 0; r < 4; r++) d[mt][nt][r] = 0.0f;

    for (int ch = 0; ch < NCH; ch++) {
        // convert staged chunk to bf16 hi/lo and store
        {
            float s = 1.0f;
            if (SCALE) s = ssc[ch * 64 + kr];
            __nv_bfloat162 hb[16], lb[16];
#pragma unroll
            for (int j = 0; j < 16; j++) {
                float a = vv[2 * j] * (SCALE ? s : 1.0f);
                float c = vv[2 * j + 1] * (SCALE ? s : 1.0f);
                __nv_bfloat16 ah = __float2bfloat16_rn(a);
                __nv_bfloat16 ch_ = __float2bfloat16_rn(c);
                hb[j] = __nv_bfloat162(ah, ch_);
                lb[j] = __nv_bfloat162(__float2bfloat16_rn(a - __bfloat162float(ah)),
                                       __float2bfloat16_rn(c - __bfloat162float(ch_)));
            }
            int off = kr * XP + nn;
#pragma unroll
            for (int q = 0; q < 4; q++) {
                *(uint4*)&sXh[off + 8 * q] = ((uint4*)hb)[q];
                *(uint4*)&sXl[off + 8 * q] = ((uint4*)lb)[q];
            }
        }
        __syncthreads();

        // prefetch next chunk while MMAs run
        if (ch + 1 < NCH) {
            const float* xp = Xp + ((size_t)b * CK + (ch + 1) * 64 + kr) * HW + p0 + nn;
#pragma unroll
            for (int q = 0; q < 8; q++) {
                float4 f = *(const float4*)(xp + q * 4);
                vv[4 * q + 0] = f.x; vv[4 * q + 1] = f.y;
                vv[4 * q + 2] = f.z; vv[4 * q + 3] = f.w;
            }
        }

#pragma unroll
        for (int ks = 0; ks < 4; ks++) {
            const int kk = ch * 64 + ks * 16;
            uint32_t ah[2][4], al[2][4];
#pragma unroll
            for (int mt = 0; mt < 2; mt++) {
                int arow = m0 + mt * 16 + (lane & 15);
                int acol = kk + (lane >> 4) * 8;
                uint32_t aoff = (uint32_t)(arow * WP + acol) * 2;
                ldsm_x4(ah[mt], uWh + aoff);
                ldsm_x4(al[mt], uWl + aoff);
            }
            uint32_t bh[4][2], bl[4][2];
#pragma unroll
            for (int nt = 0; nt < 4; nt++) {
                int brow = ks * 16 + (lane & 15);
                int bcol = nc0 + nt * 8;
                uint32_t boff = (uint32_t)(brow * XP + bcol) * 2;
                ldsm_x2t(bh[nt], uXh + boff);
                ldsm_x2t(bl[nt], uXl + boff);
            }
#pragma unroll
            for (int mt = 0; mt < 2; mt++)
#pragma unroll
                for (int nt = 0; nt < 4; nt++) {
                    mma_bf16(d[mt][nt], ah[mt], bh[nt]);
                    mma_bf16(d[mt][nt], ah[mt], bl[nt]);
                    mma_bf16(d[mt][nt], al[mt], bh[nt]);
                }
        }
        __syncthreads();
    }

    // Epilogue: add bias, store fp32
    float* Yp = SCALE ? Yout : g_y;
    const int rr = lane >> 2;
    const int cq = (lane & 3) * 2;
#pragma unroll
    for (int mt = 0; mt < 2; mt++) {
        int m = m0 + mt * 16 + rr;
        float bv0 = __ldg(bias + m);
        float bv1 = __ldg(bias + m + 8);
#pragma unroll
        for (int nt = 0; nt < 4; nt++) {
            int n = nc0 + nt * 8 + cq;
            float2 v0 = make_float2(d[mt][nt][0] + bv0, d[mt][nt][1] + bv0);
            float2 v1 = make_float2(d[mt][nt][2] + bv1, d[mt][nt][3] + bv1);
            *(float2*)&Yp[((size_t)b * 64 + m) * HW + p0 + n] = v0;
            *(float2*)&Yp[((size_t)b * 64 + m + 8) * HW + p0 + n] = v1;
        }
    }
}

// ---------------------------------------------------------------------------
// Stage B (row-streaming): one block per (band, plane); thread t = column t.
// Full image width per block -> no horizontal halo, no div/mod.
// Pipeline per row j: y row -> smem (dbl buf); hgauss (5 LDS); vgauss in a
// 5-deep register window; sm row -> smem (dbl buf, 1-col zero pads); 3x3
// Scharr/Laplacian from a 6-reg rolling window + 3 fresh LDS. One sync/row.
// sm outside the image is ZERO (matches reference zero-padding of sm).
// ---------------------------------------------------------------------------
__global__ __launch_bounds__(256)
void k_edge() {
    __shared__ float yb[2][264];    // y row + 2-pad each side (cols at +2)
    __shared__ float smr[2][264];   // sm row + 1-pad each side (cols at +1)
    __shared__ float red[256];

    const int t = threadIdx.x;
    const int z = blockIdx.y;
    const int r0 = blockIdx.x * 64;
    const float* yp = g_y + (size_t)z * HW;
    float* ep = g_edge + (size_t)z * HW;

    if (t < 2) {
        yb[0][t] = 0.f; yb[1][t] = 0.f;
        yb[0][258 + t] = 0.f; yb[1][258 + t] = 0.f;
    }
    if (t == 0) {
        smr[0][0] = 0.f; smr[1][0] = 0.f;
        smr[0][257] = 0.f; smr[1][257] = 0.f;
    }
    __syncthreads();

    float w0 = 0.f, w1 = 0.f, w2 = 0.f, w3 = 0.f, w4 = 0.f;
    float a0 = 0.f, a1 = 0.f, a2 = 0.f, b0 = 0.f, b1 = 0.f, b2 = 0.f;
    float smv_prev = 0.f;
    float tmax = 0.f, tsum = 0.f;

    int j = r0 - 3;
    float yv = (j >= 0) ? yp[j * IMG + t] : 0.f;

#pragma unroll 4
    for (; j <= r0 + 67; ++j) {
        const int bu = j & 1;
        yb[bu][t + 2] = yv;
        smr[bu][t + 1] = smv_prev;   // sm row j-3
        __syncthreads();

        // prefetch next y row
        const int jn = j + 1;
        yv = (jn >= 0 && jn < IMG) ? yp[jn * IMG + t] : 0.f;

        // horizontal gaussian at row j
        const float* Y = yb[bu];
        float h = G0 * (Y[t] + Y[t + 4]) + G1 * (Y[t + 1] + Y[t + 3]) + G2 * Y[t + 2];
        w0 = w1; w1 = w2; w2 = w3; w3 = w4; w4 = h;

        // vertical gaussian -> sm row s = j-2 (masked to 0 outside image)
        const int s = j - 2;
        float smv = G0 * (w0 + w4) + G1 * (w1 + w3) + G2 * w2;
        if (s < 0 || s >= IMG) smv = 0.f;

        // edge row e = j-4: a = sm[e-1], b = sm[e], c = sm[e+1] (just stored)
        const float* S = smr[bu];
        float c0 = S[t], c1 = S[t + 1], c2 = S[t + 2];
        const int e = j - 4;
        if (e >= r0 && e < r0 + 64) {
            float gx = 3.f * (a0 - a2) + 10.f * (b0 - b2) + 3.f * (c0 - c2);
            float gy = 3.f * (a0 - c0) + 10.f * (a1 - c1) + 3.f * (a2 - c2);
            float lap = 4.f * b1 - a1 - c1 - b0 - b2;
            float ev = fmaxf(fabsf(gx), fabsf(gy)) + 0.1f * fabsf(lap);
            ep[e * IMG + t] = ev;
            tmax = fmaxf(tmax, ev);
            tsum += ev;
        }
        a0 = b0; a1 = b1; a2 = b2;
        b0 = c0; b1 = c1; b2 = c2;
        smv_prev = smv;
    }

    // block reduce max then sum
    red[t] = tmax;
    __syncthreads();
    for (int s = 128; s; s >>= 1) {
        if (t < s) red[t] = fmaxf(red[t], red[t + s]);
        __syncthreads();
    }
    if (t == 0) atomicMax(&g_maxbits, __float_as_uint(red[0]));
    __syncthreads();
    red[t] = tsum;
    __syncthreads();
    for (int s = 128; s; s >>= 1) {
        if (t < s) red[t] += red[t + s];
        __syncthreads();
    }
    if (t == 0) atomicAdd(&g_csum[z], red[0]);
}

// ---------------------------------------------------------------------------
// Stage C: SE head.
// ---------------------------------------------------------------------------
__global__ void k_se(const float* __restrict__ w_fc1, const float* __restrict__ b_fc1,
                     const float* __restrict__ w_fc2, const float* __restrict__ b_fc2) {
    __shared__ float pooled[NB * CMID];
    __shared__ float hbuf[NB * 4];
    const int tid = threadIdx.x;
    const float maxv = __uint_as_float(g_maxbits);
    const float inv = 1.0f / (maxv + 1e-8f);

    pooled[tid] = g_csum[tid] * inv * (1.0f / 65536.0f);
    __syncthreads();
    if (tid < NB * 4) {
        int b = tid >> 2, j = tid & 3;
        float a = b_fc1[j];
        for (int c = 0; c < 64; c++) a += w_fc1[j * 64 + c] * pooled[b * 64 + c];
        hbuf[tid] = a > 0.0f ? a : 0.0f;
    }
    __syncthreads();
    {
        int b = tid >> 6, c = tid & 63;
        float a = b_fc2[c];
        for (int j = 0; j < 4; j++) a += w_fc2[c * 4 + j] * hbuf[b * 4 + j];
        float sc = 1.0f / (1.0f + expf(-a));
        g_seff[tid] = sc * inv;
    }
}

// ---------------------------------------------------------------------------
extern "C" void kernel_launch(void* const* d_in, const int* in_sizes, int n_in,
                              void* d_out, int out_size) {
    const float* x     = (const float*)d_in[0];
    const float* w_in  = (const float*)d_in[1];
    const float* b_in  = (const float*)d_in[2];
    const float* w_fc1 = (const float*)d_in[3];
    const float* b_fc1 = (const float*)d_in[4];
    const float* w_fc2 = (const float*)d_in[5];
    const float* b_fc2 = (const float*)d_in[6];
    const float* w_out = (const float*)d_in[7];
    const float* b_out = (const float*)d_in[8];
    float* out = (float*)d_out;

    const int SM_IN  = (2 * 64 * (256 + 8) + 2 * 64 * 136) * 2 + 256;  // 102912
    const int SM_OUT = (2 * 64 * (64 + 8) + 2 * 64 * 136) * 2 + 256;   // 53504
    cudaFuncSetAttribute((const void*)k_gemm<256, false>,
                         cudaFuncAttributeMaxDynamicSharedMemorySize, SM_IN);
    cudaFuncSetAttribute((const void*)k_gemm<64, true>,
                         cudaFuncAttributeMaxDynamicSharedMemorySize, SM_OUT);

    k_init<<<1, 256>>>();
    k_prep<<<64, 256>>>(w_in, w_out);
    dim3 ga(512, NB);
    k_gemm<256, false><<<ga, 256, SM_IN>>>(x, b_in, nullptr);
    dim3 gb(4, NB * CMID);
    k_edge<<<gb, 256>>>();
    k_se<<<1, 256>>>(w_fc1, b_fc1, w_fc2, b_fc2);
    k_gemm<64, true><<<ga, 256, SM_OUT>>>(nullptr, b_out, out);
}

// round 11
// speedup vs baseline: 1.2364x; 1.2364x over previous
#include <cuda_runtime.h>
#include <cuda_bf16.h>
#include <cstdint>
#include <math.h>

#define HW 65536
#define IMG 256
#define CIN 256
#define CMID 64
#define NB 4

// Scratch (device globals; allocation is forbidden)
__device__ float g_y[NB * CMID * HW];      // conv1x1-in output (64 MiB)
__device__ float g_edge[NB * CMID * HW];   // unnormalized edge  (64 MiB)
__device__ unsigned g_maxbits;             // global max (float bits, values >= 0)
__device__ float g_csum[NB * CMID];        // per-(b,c) sums of edge
__device__ float g_seff[NB * CMID];        // sigmoid(se)*inv_max per (b,c)

// Pre-split weights (bf16 hi/lo)
__device__ __align__(16) __nv_bfloat16 g_win_hi[64 * 256];
__device__ __align__(16) __nv_bfloat16 g_win_lo[64 * 256];
__device__ __align__(16) __nv_bfloat16 g_wout_hi[64 * 64];
__device__ __align__(16) __nv_bfloat16 g_wout_lo[64 * 64];

// 1D gaussian (sigma=2, size=5), normalized: exp(-r^2/8)/sum
#define G0 0.15246915f
#define G1 0.22184120f
#define G2 0.25137913f

// Split fp32 weights into bf16 hi/lo pairs; block 0 also resets reductions.
__global__ void k_prep(const float* __restrict__ w_in, const float* __restrict__ w_out) {
    int i = blockIdx.x * 256 + threadIdx.x;
    if (blockIdx.x == 0) {
        if (threadIdx.x == 0) g_maxbits = 0u;
        if (threadIdx.x < NB * CMID) g_csum[threadIdx.x] = 0.0f;
    }
    if (i < 64 * 256) {
        float w = w_in[i];
        __nv_bfloat16 h = __float2bfloat16_rn(w);
        g_win_hi[i] = h;
        g_win_lo[i] = __float2bfloat16_rn(w - __bfloat162float(h));
    }
    if (i < 64 * 64) {
        float w = w_out[i];
        __nv_bfloat16 h = __float2bfloat16_rn(w);
        g_wout_hi[i] = h;
        g_wout_lo[i] = __float2bfloat16_rn(w - __bfloat162float(h));
    }
}

// ---------------------------------------------------------------------------
// Tensor-core 1x1 conv:  Y[b,o,p] = bias[o] + sum_c W[o,c] * X[b,c,p]
// M=64 (o), N_TILE=64 pixels, K=CK. 3-GEMM bf16 split for fp32-grade accuracy.
// 8 warps, each warp: m32 x n16. K processed in chunks of 64 with LDG prefetch.
// (Round-5 proven configuration; NT=128 variant regressed via reg pressure.)
// ---------------------------------------------------------------------------
__device__ __forceinline__ void mma_bf16(float* d, const uint32_t* a, const uint32_t* b) {
    asm volatile(
        "mma.sync.aligned.m16n8k16.row.col.f32.bf16.bf16.f32 "
        "{%0,%1,%2,%3}, {%4,%5,%6,%7}, {%8,%9}, {%0,%1,%2,%3};\n"
        : "+f"(d[0]), "+f"(d[1]), "+f"(d[2]), "+f"(d[3])
        : "r"(a[0]), "r"(a[1]), "r"(a[2]), "r"(a[3]), "r"(b[0]), "r"(b[1]));
}
__device__ __forceinline__ void ldsm_x4(uint32_t* r, uint32_t addr) {
    asm volatile("ldmatrix.sync.aligned.m8n8.x4.shared.b16 {%0,%1,%2,%3}, [%4];"
                 : "=r"(r[0]), "=r"(r[1]), "=r"(r[2]), "=r"(r[3]) : "r"(addr));
}
__device__ __forceinline__ void ldsm_x2t(uint32_t* r, uint32_t addr) {
    asm volatile("ldmatrix.sync.aligned.m8n8.x2.trans.shared.b16 {%0,%1}, [%2];"
                 : "=r"(r[0]), "=r"(r[1]) : "r"(addr));
}

template <int CK, bool SCALE>
__global__ __launch_bounds__(256, 2)
void k_gemm(const float* __restrict__ Xin, const float* __restrict__ bias,
            float* __restrict__ Yout) {
    constexpr int WP = CK + 8;     // W smem pitch (bf16 elems)
    constexpr int XP = 72;         // X smem pitch
    constexpr int NCH = CK / 64;   // K chunks

    extern __shared__ char smem_raw[];
    __nv_bfloat16* sWh = (__nv_bfloat16*)smem_raw;
    __nv_bfloat16* sWl = sWh + 64 * WP;
    __nv_bfloat16* sXh = sWl + 64 * WP;
    __nv_bfloat16* sXl = sXh + 64 * XP;
    float* ssc = (float*)(sXl + 64 * XP);

    const int tid = threadIdx.x;
    const int lane = tid & 31;
    const int wid = tid >> 5;
    const int b = blockIdx.y;
    const int p0 = blockIdx.x * 64;

    const float* Xp = SCALE ? (const float*)g_edge : Xin;
    const __nv_bfloat16* gWh = SCALE ? g_wout_hi : g_win_hi;
    const __nv_bfloat16* gWl = SCALE ? g_wout_lo : g_win_lo;

    // Stage weights (bf16 hi/lo) into padded smem
    for (int i = tid; i < 64 * CK / 8; i += 256) {
        int m = i / (CK / 8);
        int c = (i % (CK / 8)) * 8;
        *(uint4*)&sWh[m * WP + c] = ((const uint4*)gWh)[i];
        *(uint4*)&sWl[m * WP + c] = ((const uint4*)gWl)[i];
    }
    if (SCALE && tid < CK) ssc[tid] = g_seff[b * CK + tid];

    // X chunk staging assignment: thread -> (k row, 16 n-values)
    const int kr = tid >> 2;
    const int nn = (tid & 3) * 16;
    float vv[16];
    {
        const float* xp = Xp + ((size_t)b * CK + kr) * HW + p0 + nn;
        float4 q0 = *(const float4*)(xp);
        float4 q1 = *(const float4*)(xp + 4);
        float4 q2 = *(const float4*)(xp + 8);
        float4 q3 = *(const float4*)(xp + 12);
        vv[0]=q0.x; vv[1]=q0.y; vv[2]=q0.z; vv[3]=q0.w;
        vv[4]=q1.x; vv[5]=q1.y; vv[6]=q1.z; vv[7]=q1.w;
        vv[8]=q2.x; vv[9]=q2.y; vv[10]=q2.z; vv[11]=q2.w;
        vv[12]=q3.x; vv[13]=q3.y; vv[14]=q3.z; vv[15]=q3.w;
    }
    __syncthreads();   // weights + ssc ready

    const uint32_t uWh = (uint32_t)__cvta_generic_to_shared(sWh);
    const uint32_t uWl = (uint32_t)__cvta_generic_to_shared(sWl);
    const uint32_t uXh = (uint32_t)__cvta_generic_to_shared(sXh);
    const uint32_t uXl = (uint32_t)__cvta_generic_to_shared(sXl);

    const int m0 = (wid & 1) * 32;
    const int nc0 = (wid >> 1) * 16;
    float d[2][2][4];
#pragma unroll
    for (int mt = 0; mt < 2; mt++)
#pragma unroll
        for (int nt = 0; nt < 2; nt++)
#pragma unroll
            for (int r = 0; r < 4; r++) d[mt][nt][r] = 0.0f;

    for (int ch = 0; ch < NCH; ch++) {
        // convert staged chunk to bf16 hi/lo and store
        {
            float s = 1.0f;
            if (SCALE) s = ssc[ch * 64 + kr];
            __nv_bfloat162 hb[8], lb[8];
#pragma unroll
            for (int j = 0; j < 8; j++) {
                float a = vv[2 * j] * (SCALE ? s : 1.0f);
                float c = vv[2 * j + 1] * (SCALE ? s : 1.0f);
                __nv_bfloat16 ah = __float2bfloat16_rn(a);
                __nv_bfloat16 ch_ = __float2bfloat16_rn(c);
                hb[j] = __nv_bfloat162(ah, ch_);
                lb[j] = __nv_bfloat162(__float2bfloat16_rn(a - __bfloat162float(ah)),
                                       __float2bfloat16_rn(c - __bfloat162float(ch_)));
            }
            int off = kr * XP + nn;
            *(uint4*)&sXh[off] = ((uint4*)hb)[0];
            *(uint4*)&sXh[off + 8] = ((uint4*)hb)[1];
            *(uint4*)&sXl[off] = ((uint4*)lb)[0];
            *(uint4*)&sXl[off + 8] = ((uint4*)lb)[1];
        }
        __syncthreads();

        // prefetch next chunk while MMAs run
        if (ch + 1 < NCH) {
            const float* xp = Xp + ((size_t)b * CK + (ch + 1) * 64 + kr) * HW + p0 + nn;
            float4 q0 = *(const float4*)(xp);
            float4 q1 = *(const float4*)(xp + 4);
            float4 q2 = *(const float4*)(xp + 8);
            float4 q3 = *(const float4*)(xp + 12);
            vv[0]=q0.x; vv[1]=q0.y; vv[2]=q0.z; vv[3]=q0.w;
            vv[4]=q1.x; vv[5]=q1.y; vv[6]=q1.z; vv[7]=q1.w;
            vv[8]=q2.x; vv[9]=q2.y; vv[10]=q2.z; vv[11]=q2.w;
            vv[12]=q3.x; vv[13]=q3.y; vv[14]=q3.z; vv[15]=q3.w;
        }

#pragma unroll
        for (int ks = 0; ks < 4; ks++) {
            const int kk = ch * 64 + ks * 16;
            uint32_t ah[2][4], al[2][4];
#pragma unroll
            for (int mt = 0; mt < 2; mt++) {
                int arow = m0 + mt * 16 + (lane & 15);
                int acol = kk + (lane >> 4) * 8;
                uint32_t aoff = (uint32_t)(arow * WP + acol) * 2;
                ldsm_x4(ah[mt], uWh + aoff);
                ldsm_x4(al[mt], uWl + aoff);
            }
            uint32_t bh[2][2], bl[2][2];
#pragma unroll
            for (int nt = 0; nt < 2; nt++) {
                int brow = ks * 16 + (lane & 15);
                int bcol = nc0 + nt * 8;
                uint32_t boff = (uint32_t)(brow * XP + bcol) * 2;
                ldsm_x2t(bh[nt], uXh + boff);
                ldsm_x2t(bl[nt], uXl + boff);
            }
#pragma unroll
            for (int mt = 0; mt < 2; mt++)
#pragma unroll
                for (int nt = 0; nt < 2; nt++) {
                    mma_bf16(d[mt][nt], ah[mt], bh[nt]);
                    mma_bf16(d[mt][nt], ah[mt], bl[nt]);
                    mma_bf16(d[mt][nt], al[mt], bh[nt]);
                }
        }
        __syncthreads();
    }

    // Epilogue: add bias, store fp32
    float* Yp = SCALE ? Yout : g_y;
    const int rr = lane >> 2;
    const int cq = (lane & 3) * 2;
#pragma unroll
    for (int mt = 0; mt < 2; mt++) {
        int m = m0 + mt * 16 + rr;
        float bv0 = __ldg(bias + m);
        float bv1 = __ldg(bias + m + 8);
#pragma unroll
        for (int nt = 0; nt < 2; nt++) {
            int n = nc0 + nt * 8 + cq;
            float2 v0 = make_float2(d[mt][nt][0] + bv0, d[mt][nt][1] + bv0);
            float2 v1 = make_float2(d[mt][nt][2] + bv1, d[mt][nt][3] + bv1);
            *(float2*)&Yp[((size_t)b * 64 + m) * HW + p0 + n] = v0;
            *(float2*)&Yp[((size_t)b * 64 + m + 8) * HW + p0 + n] = v1;
        }
    }
}

// ---------------------------------------------------------------------------
// Stage B (row-streaming): one block per (32-row band, plane); thread t = col t.
// Full image width per block -> no horizontal halo, no div/mod.
// Per row j: y row -> smem (dbl buf); hgauss (5 LDS); vgauss in a 5-deep
// register window; sm row -> smem (dbl buf, zero pads); 3x3 Scharr/Laplacian
// from a 6-reg rolling window + 3 fresh LDS. One sync/row.
// ---------------------------------------------------------------------------
#define BAND 32
__global__ __launch_bounds__(256)
void k_edge() {
    __shared__ float yb[2][264];    // y row + 2-pad each side (cols at +2)
    __shared__ float smr[2][264];   // sm row + 1-pad each side (cols at +1)
    __shared__ float red[256];

    const int t = threadIdx.x;
    const int z = blockIdx.y;
    const int r0 = blockIdx.x * BAND;
    const float* yp = g_y + (size_t)z * HW;
    float* ep = g_edge + (size_t)z * HW;

    if (t < 2) {
        yb[0][t] = 0.f; yb[1][t] = 0.f;
        yb[0][258 + t] = 0.f; yb[1][258 + t] = 0.f;
    }
    if (t == 0) {
        smr[0][0] = 0.f; smr[1][0] = 0.f;
        smr[0][257] = 0.f; smr[1][257] = 0.f;
    }
    __syncthreads();

    float w0 = 0.f, w1 = 0.f, w2 = 0.f, w3 = 0.f, w4 = 0.f;
    float a0 = 0.f, a1 = 0.f, a2 = 0.f, b0 = 0.f, b1 = 0.f, b2 = 0.f;
    float smv_prev = 0.f;
    float tmax = 0.f, tsum = 0.f;

    int j = r0 - 3;
    float yv = (j >= 0) ? yp[j * IMG + t] : 0.f;

#pragma unroll 4
    for (; j <= r0 + BAND + 3; ++j) {
        const int bu = j & 1;
        yb[bu][t + 2] = yv;
        smr[bu][t + 1] = smv_prev;   // sm row j-3
        __syncthreads();

        // prefetch next y row
        const int jn = j + 1;
        yv = (jn >= 0 && jn < IMG) ? yp[jn * IMG + t] : 0.f;

        // horizontal gaussian at row j
        const float* Y = yb[bu];
        float h = G0 * (Y[t] + Y[t + 4]) + G1 * (Y[t + 1] + Y[t + 3]) + G2 * Y[t + 2];
        w0 = w1; w1 = w2; w2 = w3; w3 = w4; w4 = h;

        // vertical gaussian -> sm row s = j-2 (masked to 0 outside image)
        const int s = j - 2;
        float smv = G0 * (w0 + w4) + G1 * (w1 + w3) + G2 * w2;
        if (s < 0 || s >= IMG) smv = 0.f;

        // edge row e = j-4: a = sm[e-1], b = sm[e], c = sm[e+1] (just stored)
        const float* S = smr[bu];
        float c0 = S[t], c1 = S[t + 1], c2 = S[t + 2];
        const int e = j - 4;
        if (e >= r0 && e < r0 + BAND) {
            float gx = 3.f * (a0 - a2) + 10.f * (b0 - b2) + 3.f * (c0 - c2);
            float gy = 3.f * (a0 - c0) + 10.f * (a1 - c1) + 3.f * (a2 - c2);
            float lap = 4.f * b1 - a1 - c1 - b0 - b2;
            float ev = fmaxf(fabsf(gx), fabsf(gy)) + 0.1f * fabsf(lap);
            ep[e * IMG + t] = ev;
            tmax = fmaxf(tmax, ev);
            tsum += ev;
        }
        a0 = b0; a1 = b1; a2 = b2;
        b0 = c0; b1 = c1; b2 = c2;
        smv_prev = smv;
    }

    // block reduce max then sum
    red[t] = tmax;
    __syncthreads();
    for (int s = 128; s; s >>= 1) {
        if (t < s) red[t] = fmaxf(red[t], red[t + s]);
        __syncthreads();
    }
    if (t == 0) atomicMax(&g_maxbits, __float_as_uint(red[0]));
    __syncthreads();
    red[t] = tsum;
    __syncthreads();
    for (int s = 128; s; s >>= 1) {
        if (t < s) red[t] += red[t + s];
        __syncthreads();
    }
    if (t == 0) atomicAdd(&g_csum[z], red[0]);
}

// ---------------------------------------------------------------------------
// Stage C: SE head.
// ---------------------------------------------------------------------------
__global__ void k_se(const float* __restrict__ w_fc1, const float* __restrict__ b_fc1,
                     const float* __restrict__ w_fc2, const float* __restrict__ b_fc2) {
    __shared__ float pooled[NB * CMID];
    __shared__ float hbuf[NB * 4];
    const int tid = threadIdx.x;
    const float maxv = __uint_as_float(g_maxbits);
    const float inv = 1.0f / (maxv + 1e-8f);

    pooled[tid] = g_csum[tid] * inv * (1.0f / 65536.0f);
    __syncthreads();
    if (tid < NB * 4) {
        int b = tid >> 2, j = tid & 3;
        float a = b_fc1[j];
        for (int c = 0; c < 64; c++) a += w_fc1[j * 64 + c] * pooled[b * 64 + c];
        hbuf[tid] = a > 0.0f ? a : 0.0f;
    }
    __syncthreads();
    {
        int b = tid >> 6, c = tid & 63;
        float a = b_fc2[c];
        for (int j = 0; j < 4; j++) a += w_fc2[c * 4 + j] * hbuf[b * 4 + j];
        float sc = 1.0f / (1.0f + expf(-a));
        g_seff[tid] = sc * inv;
    }
}

// ---------------------------------------------------------------------------
extern "C" void kernel_launch(void* const* d_in, const int* in_sizes, int n_in,
                              void* d_out, int out_size) {
    const float* x     = (const float*)d_in[0];
    const float* w_in  = (const float*)d_in[1];
    const float* b_in  = (const float*)d_in[2];
    const float* w_fc1 = (const float*)d_in[3];
    const float* b_fc1 = (const float*)d_in[4];
    const float* w_fc2 = (const float*)d_in[5];
    const float* b_fc2 = (const float*)d_in[6];
    const float* w_out = (const float*)d_in[7];
    const float* b_out = (const float*)d_in[8];
    float* out = (float*)d_out;

    const int SM_IN  = (2 * 64 * (256 + 8) + 2 * 64 * 72) * 2 + 256;    // 86272
    const int SM_OUT = (2 * 64 * (64 + 8) + 2 * 64 * 72) * 2 + 256;     // 37120
    cudaFuncSetAttribute((const void*)k_gemm<256, false>,
                         cudaFuncAttributeMaxDynamicSharedMemorySize, SM_IN);
    cudaFuncSetAttribute((const void*)k_gemm<64, true>,
                         cudaFuncAttributeMaxDynamicSharedMemorySize, SM_OUT);

    k_prep<<<64, 256>>>(w_in, w_out);
    dim3 ga(1024, NB);
    k_gemm<256, false><<<ga, 256, SM_IN>>>(x, b_in, nullptr);
    dim3 gb(IMG / BAND, NB * CMID);
    k_edge<<<gb, 256>>>();
    k_se<<<1, 256>>>(w_fc1, b_fc1, w_fc2, b_fc2);
    k_gemm<64, true><<<ga, 256, SM_OUT>>>(nullptr, b_out, out);
}